// round 6
// baseline (speedup 1.0000x reference)
#include <cuda_runtime.h>
#include <cuda_bf16.h>
#include <math.h>
#include <stdint.h>

#define BSZ  4
#define TLEN 2048
#define DIN_ 512
#define DM_  1024
#define DO_  1024
#define LNUM 2
#define DS_  16
#define DC_  4
#define DI_  2048
#define DTR_ 64
#define MROWS (BSZ*TLEN)          // 8192
#define DBCW  (DTR_ + 2*DS_)      // 96

// ---------------- scratch (device globals; no allocation allowed) -----------
__device__ float g_x   [(size_t)MROWS*DM_];
__device__ float g_xn  [(size_t)MROWS*DM_];   // LN out; reused as mean partials
__device__ float g_xz  [(size_t)MROWS*2*DI_];
__device__ float g_u   [(size_t)MROWS*DI_];
__device__ float g_dbc [(size_t)MROWS*DBCW];
__device__ float g_delta[(size_t)MROWS*DI_];
__device__ float g_y   [(size_t)MROWS*DI_];
__device__ float g_ob  [(size_t)MROWS*DO_];   // also x_proj split-K scratch
__device__ int   g_len [BSZ];
// split-precision bf16 operand buffers
__device__ __nv_bfloat16 g_abig[(size_t)MROWS*6144];   // M x 3K
__device__ __nv_bfloat16 g_wbig[(size_t)4096*3072];    // N x 3K

// =================== PTX helpers (baseline compute_103 ISA) =================
__device__ __forceinline__ uint32_t smem_u32(const void* p) {
    uint32_t a;
    asm("{ .reg .u64 t; cvta.to.shared.u64 t, %1; cvt.u32.u64 %0, t; }" : "=r"(a) : "l"(p));
    return a;
}
__device__ __forceinline__ void cp_async16(uint32_t d, const void* g, int sz) {
    asm volatile("cp.async.cg.shared.global [%0], [%1], 16, %2;"
                 :: "r"(d), "l"(g), "r"(sz) : "memory");
}
__device__ __forceinline__ void ldm4(uint32_t* r, uint32_t addr) {
    asm volatile("ldmatrix.sync.aligned.m8n8.x4.shared.b16 {%0,%1,%2,%3}, [%4];"
        : "=r"(r[0]), "=r"(r[1]), "=r"(r[2]), "=r"(r[3]) : "r"(addr));
}
__device__ __forceinline__ void mma16816(float* d, const uint32_t* a,
                                         uint32_t b0, uint32_t b1) {
    asm volatile("mma.sync.aligned.m16n8k16.row.col.f32.bf16.bf16.f32 "
        "{%0,%1,%2,%3}, {%4,%5,%6,%7}, {%8,%9}, {%0,%1,%2,%3};"
        : "+f"(d[0]), "+f"(d[1]), "+f"(d[2]), "+f"(d[3])
        : "r"(a[0]), "r"(a[1]), "r"(a[2]), "r"(a[3]), "r"(b0), "r"(b1));
}

// ---------------- split conversion: v -> (hi, lo) bf16, K tripled -----------
// mode 0 (activations): [hi | hi | lo] ; mode 1 (weights): [hi | lo | hi]
__global__ void convert_split(const float* __restrict__ src, int lda,
                              __nv_bfloat16* __restrict__ dst,
                              int rows, int K, int mode)
{
    size_t idx = (size_t)blockIdx.x * blockDim.x + threadIdx.x;
    if (idx >= (size_t)rows * K) return;
    int row = (int)(idx / K);
    int c   = (int)(idx % K);
    float v = src[(size_t)row * lda + c];
    __nv_bfloat16 hi = __float2bfloat16(v);
    __nv_bfloat16 lo = __float2bfloat16(v - __bfloat162float(hi));
    size_t base = (size_t)row * (3 * (size_t)K);
    if (mode == 0) {
        dst[base + c] = hi; dst[base + K + c] = hi; dst[base + 2*K + c] = lo;
    } else {
        dst[base + c] = hi; dst[base + K + c] = lo; dst[base + 2*K + c] = hi;
    }
}

// ---------------- mma.sync bf16 GEMM: C = Abig(M x K3) * Wbig(N x K3)^T -----
// CTA tile 128x128, 8 warps (2M x 4N), warp tile 64x32, BK=64, 3 stages.
// gridDim.z = split-K parts.
#define STAGES 3
#define STAGE_BYTES 32768u
#define GTC_SMEM (STAGES * STAGE_BYTES)

__global__ __launch_bounds__(256, 2)
void gemm_mma(const __nv_bfloat16* __restrict__ A, int lda3,
              const __nv_bfloat16* __restrict__ W, int ldb3,
              const float* __restrict__ bias,
              float* __restrict__ C, int ldc,
              int N, int K3, int kbase, int nch, int partStride, int flags)
{
    extern __shared__ char smem[];
    const uint32_t sbase = smem_u32(smem);
    const int tid  = threadIdx.x;
    const int lane = tid & 31, wid = tid >> 5;
    const int bm = blockIdx.y << 7, bn = blockIdx.x << 7;
    const int warpM = (wid & 1) << 6;
    const int warpN = (wid >> 1) << 5;

    const int part = blockIdx.z;
    const int kb   = kbase + part * (nch << 6);
    C += (size_t)part * partStride;

    float acc[4][4][4];
#pragma unroll
    for (int i = 0; i < 4; i++)
#pragma unroll
        for (int j = 0; j < 4; j++)
#pragma unroll
            for (int k = 0; k < 4; k++) acc[i][j][k] = 0.f;

    const int ldch  = tid & 7;
    const int ldrow = tid >> 3;
    const uint32_t swz = (uint32_t)((ldch ^ (ldrow & 7)) << 4);
    const uint32_t loff0 = (uint32_t)ldrow * 128u + swz;
    const __nv_bfloat16* pA[4];
    const __nv_bfloat16* pW[4];
    int  bok[4];
    {
        const int k0 = kb + (ldch << 3);
#pragma unroll
        for (int i = 0; i < 4; i++) {
            const int row = ldrow + (i << 5);
            pA[i] = A + (size_t)(bm + row) * lda3 + k0;
            const int brow = bn + row;
            bok[i] = (brow < N);
            pW[i] = W + (size_t)(bok[i] ? brow : 0) * ldb3 + k0;
        }
    }
    int kk = kb + (ldch << 3);

    const int r_a   = (lane & 7) + ((lane >> 3) & 1) * 8;
    const int cpart = lane >> 4;
    const int rx    = lane & 7;
    uint32_t a_row[4], b_row[2], csel[4];
#pragma unroll
    for (int mi = 0; mi < 4; mi++) a_row[mi] = (uint32_t)(warpM + mi*16 + r_a) * 128u;
#pragma unroll
    for (int bi = 0; bi < 2; bi++) b_row[bi] = 16384u + (uint32_t)(warpN + bi*16 + r_a) * 128u;
#pragma unroll
    for (int ks = 0; ks < 4; ks++) csel[ks] = (uint32_t)(((2*ks + cpart) ^ rx) << 4);

    int ldstg = 0;
    auto load_stage = [&]() {
        const uint32_t sbs = sbase + (uint32_t)ldstg * STAGE_BYTES;
        const int aok = (kk < K3) ? 16 : 0;
#pragma unroll
        for (int i = 0; i < 4; i++) {
            const uint32_t off = loff0 + (uint32_t)(i << 12);
            cp_async16(sbs + off, pA[i], aok);
            cp_async16(sbs + 16384u + off, pW[i], bok[i] ? aok : 0);
            pA[i] += 64; pW[i] += 64;
        }
        kk += 64;
        asm volatile("cp.async.commit_group;" ::: "memory");
        ldstg = (ldstg + 1 == STAGES) ? 0 : ldstg + 1;
    };

    for (int s = 0; s < STAGES - 1 && s < nch; s++) load_stage();

    int cstg = 0;
    for (int c = 0; c < nch; c++) {
        asm volatile("cp.async.wait_group %0;" :: "n"(STAGES - 2) : "memory");
        __syncthreads();
        const uint32_t sA = sbase + (uint32_t)cstg * STAGE_BYTES;
        cstg = (cstg + 1 == STAGES) ? 0 : cstg + 1;
#pragma unroll
        for (int ks = 0; ks < 4; ks++) {
            uint32_t af[4][4], bf[2][4];
#pragma unroll
            for (int mi = 0; mi < 4; mi++) ldm4(af[mi], sA + a_row[mi] + csel[ks]);
#pragma unroll
            for (int bi = 0; bi < 2; bi++) ldm4(bf[bi], sA + b_row[bi] + csel[ks]);
#pragma unroll
            for (int mi = 0; mi < 4; mi++) {
#pragma unroll
                for (int ni = 0; ni < 4; ni++) {
                    const int bi = ni >> 1, sel = ni & 1;
                    mma16816(acc[mi][ni], af[mi], bf[bi][sel], bf[bi][sel + 2]);
                }
            }
        }
        if (c + STAGES - 1 < nch) load_stage();
    }

    const int g = lane >> 2;
    const int ncol = (lane & 3) * 2;
#pragma unroll
    for (int mi = 0; mi < 4; mi++) {
        const int m0 = bm + warpM + mi*16 + g;
#pragma unroll
        for (int ni = 0; ni < 4; ni++) {
            const int n = bn + warpN + ni*8 + ncol;
            if (n >= N) continue;
            float v[4] = {acc[mi][ni][0], acc[mi][ni][1], acc[mi][ni][2], acc[mi][ni][3]};
            if (bias) {
                float b0 = bias[n], b1 = bias[n+1];
                v[0] += b0; v[1] += b1; v[2] += b0; v[3] += b1;
            }
            if (flags & 2) {
#pragma unroll
                for (int k = 0; k < 4; k++)
                    v[k] = (v[k] > 20.f) ? v[k] : log1pf(expf(v[k]));
            }
            float* p0 = C + (size_t)m0 * ldc + n;
            float* p1 = C + (size_t)(m0 + 8) * ldc + n;
            if (flags & 1) {
                float2 o0 = *(const float2*)p0, o1 = *(const float2*)p1;
                v[0] += o0.x; v[1] += o0.y; v[2] += o1.x; v[3] += o1.y;
            }
            *(float2*)p0 = make_float2(v[0], v[1]);
            *(float2*)p1 = make_float2(v[2], v[3]);
        }
    }
}

// ---------------- split-K reduce ---------------------------------------------
__global__ void reduce4_kernel(float* __restrict__ dst,
                               const float* __restrict__ part, int n)
{
    int i = blockIdx.x * blockDim.x + threadIdx.x;
    if (i < n)
        dst[i] = ((part[i] + part[i + n]) + (part[i + 2*n] + part[i + 3*n]));
}

// ---------------- mask decoding ---------------------------------------------
__global__ void detect_mask_kernel(const unsigned char* __restrict__ mb) {
    __shared__ int s_weird, s_off, s_cnt[BSZ];
    int tid = threadIdx.x;
    if (tid == 0) { s_weird = 0; s_off = 0; }
    if (tid < BSZ) s_cnt[tid] = 0;
    __syncthreads();
    for (int i = tid; i < BSZ*TLEN; i += blockDim.x) {
        unsigned char c = mb[i];
        if (c > 1) s_weird = 1;
        else if (c && (i & 3)) s_off = 1;
    }
    __syncthreads();
    int mode = s_weird ? 2 : (s_off ? 0 : 1);
    for (int i = tid; i < BSZ*TLEN; i += blockDim.x) {
        int b = i / TLEN;
        int v;
        if (mode == 0)      v = mb[i];
        else if (mode == 1) v = ((const int*)mb)[i];
        else                v = (((const float*)mb)[i] != 0.0f);
        if (!v) atomicAdd(&s_cnt[b], 1);
    }
    __syncthreads();
    if (tid < BSZ) g_len[tid] = s_cnt[tid];
}

// ---------------- layernorm -------------------------------------------------
__global__ void layernorm_kernel(const float* __restrict__ x,
                                 const float* __restrict__ w,
                                 const float* __restrict__ bb,
                                 float* __restrict__ y)
{
    int row = blockIdx.x, tid = threadIdx.x;
    const float* xr = x + (size_t)row * DM_;
    float4 v = *(const float4*)(xr + tid * 4);
    float s  = v.x + v.y + v.z + v.w;
    float ss = v.x*v.x + v.y*v.y + v.z*v.z + v.w*v.w;
#pragma unroll
    for (int o = 16; o > 0; o >>= 1) {
        s  += __shfl_xor_sync(0xffffffffu, s, o);
        ss += __shfl_xor_sync(0xffffffffu, ss, o);
    }
    __shared__ float rs_[8], rss[8];
    int wid = tid >> 5, lane = tid & 31;
    if (lane == 0) { rs_[wid] = s; rss[wid] = ss; }
    __syncthreads();
    if (tid == 0) {
        float ts = 0.f, tss = 0.f;
        for (int i = 0; i < 8; i++) { ts += rs_[i]; tss += rss[i]; }
        rs_[0] = ts; rss[0] = tss;
    }
    __syncthreads();
    float mu  = rs_[0] * (1.f / DM_);
    float var = rss[0] * (1.f / DM_) - mu * mu;
    float inv = rsqrtf(var + 1e-5f);
    float4 wv = *(const float4*)(w + tid * 4);
    float4 bv = *(const float4*)(bb + tid * 4);
    float4 o;
    o.x = (v.x - mu) * inv * wv.x + bv.x;
    o.y = (v.y - mu) * inv * wv.y + bv.y;
    o.z = (v.z - mu) * inv * wv.z + bv.z;
    o.w = (v.w - mu) * inv * wv.w + bv.w;
    *(float4*)(y + (size_t)row * DM_ + tid * 4) = o;
}

// ---------------- causal depthwise conv (DC=4) + bias + silu, float4 --------
__global__ void conv_silu_kernel(const float* __restrict__ cw,
                                 const float* __restrict__ cb)
{
    size_t idx = (size_t)blockIdx.x * blockDim.x + threadIdx.x;   // (MROWS*DI/4)
    int d4 = (int)(idx & (DI_/4 - 1));         // 0..511
    size_t r = idx >> 9;                        // row
    int t = (int)(r & (TLEN - 1));
    int d = d4 << 2;

    const float* base = g_xz + r * (size_t)(2*DI_) + d;
    float4 a = *(const float4*)(cb + d);
    float4 cwv[4];
#pragma unroll
    for (int i = 0; i < 4; i++) cwv[i] = *(const float4*)(cw + (d + i) * DC_);
#pragma unroll
    for (int j = 0; j < DC_; j++) {
        int tt = t - (DC_ - 1) + j;
        if (tt >= 0) {
            float4 xv = *(const float4*)(base + (ptrdiff_t)(j - (DC_-1)) * (2*DI_));
            a.x += xv.x * cwv[0].x * 0.f + xv.x * ((&cwv[0].x)[j]);  // placeholder avoided below
        }
    }
    // recompute cleanly (compiler folds): per-channel taps
    float acc[4];
#pragma unroll
    for (int i = 0; i < 4; i++) acc[i] = ((const float*)&a)[0]*0.f;  // zero init below
    acc[0] = cb[d+0]; acc[1] = cb[d+1]; acc[2] = cb[d+2]; acc[3] = cb[d+3];
#pragma unroll
    for (int j = 0; j < DC_; j++) {
        int tt = t - (DC_ - 1) + j;
        if (tt >= 0) {
            float4 xv = *(const float4*)(base + (ptrdiff_t)(j - (DC_-1)) * (2*DI_));
            acc[0] += xv.x * ((const float*)&cwv[0])[j];
            acc[1] += xv.y * ((const float*)&cwv[1])[j];
            acc[2] += xv.z * ((const float*)&cwv[2])[j];
            acc[3] += xv.w * ((const float*)&cwv[3])[j];
        }
    }
    float4 o;
    o.x = acc[0] / (1.f + __expf(-acc[0]));
    o.y = acc[1] / (1.f + __expf(-acc[1]));
    o.z = acc[2] / (1.f + __expf(-acc[2]));
    o.w = acc[3] / (1.f + __expf(-acc[3]));
    *(float4*)(g_u + r * DI_ + d) = o;
}

// ---------------- selective scan + fused gate (lean) ------------------------
__global__ void scan_kernel(const float* __restrict__ Alog,
                            const float* __restrict__ Dp)
{
    int gw   = (int)((blockIdx.x * blockDim.x + threadIdx.x) >> 5);
    int lane = threadIdx.x & 31;
    int b  = gw >> 10;
    int dp = gw & 1023;
    int s  = lane & 15;
    int half = lane >> 4;
    int d = dp * 2 + half;

    const float Av = -expf(Alog[d * DS_ + s]);
    const float Dv = Dp[d];
    float h = 0.f;
    const size_t brow0 = (size_t)b * TLEN;

#pragma unroll 4
    for (int t = 0; t < TLEN; t++) {
        size_t row = brow0 + t;
        float delta = g_delta[row * DI_ + d];
        float u     = g_u    [row * DI_ + d];
        float Bv = g_dbc[row * DBCW + DTR_ + s];
        float Cv = g_dbc[row * DBCW + DTR_ + DS_ + s];
        float e = __expf(delta * Av);
        h = h * e + (delta * u) * Bv;
        float p = h * Cv;
        p += __shfl_xor_sync(0xffffffffu, p, 1);
        p += __shfl_xor_sync(0xffffffffu, p, 2);
        p += __shfl_xor_sync(0xffffffffu, p, 4);
        p += __shfl_xor_sync(0xffffffffu, p, 8);
        if (s == 0) {
            float z = g_xz[row * (size_t)(2*DI_) + DI_ + d];
            float sg = z / (1.f + __expf(-z));
            g_y[row * DI_ + d] = (p + u * Dv) * sg;
        }
    }
}

// ---------------- masked mean, two phase ------------------------------------
#define MEAN_SLICES 16
__global__ void mean1_kernel(float* __restrict__ partial)   // uses g_ob as input
{
    int b = blockIdx.y, slice = blockIdx.z;
    int o = blockIdx.x * blockDim.x + threadIdx.x;
    int len = g_len[b];
    if (len < 1) len = 1;
    int t0 = slice * (TLEN / MEAN_SLICES);
    int t1 = t0 + (TLEN / MEAN_SLICES);
    if (t1 > len) t1 = len;
    float sum = 0.f;
    const float* p = g_ob + ((size_t)b * TLEN + t0) * DO_ + o;
    for (int t = t0; t < t1; t++, p += DO_) sum += *p;
    partial[((size_t)b * MEAN_SLICES + slice) * DO_ + o] = sum;
}
__global__ void mean2_kernel(const float* __restrict__ partial,
                             float* __restrict__ out)
{
    int b = blockIdx.y;
    int o = blockIdx.x * blockDim.x + threadIdx.x;
    int len = g_len[b];
    if (len < 1) len = 1;
    float sum = 0.f;
#pragma unroll
    for (int i = 0; i < MEAN_SLICES; i++)
        sum += partial[((size_t)b * MEAN_SLICES + i) * DO_ + o];
    out[b * DO_ + o] = sum / (float)len;
}

// ---------------- host-side GEMM wrapper ------------------------------------
static void run_gemm(const float* A, int lda, const float* W, int ldw,
                     const float* bias, float* C, int ldc,
                     int M, int N, int K, int flags,
                     __nv_bfloat16* abig, __nv_bfloat16* wbig)
{
    size_t na = (size_t)M * K, nw = (size_t)N * K;
    convert_split<<<(unsigned)((na + 255) / 256), 256>>>(A, lda, abig, M, K, 0);
    convert_split<<<(unsigned)((nw + 255) / 256), 256>>>(W, ldw, wbig, N, K, 1);
    int K3 = 3 * K;
    int nch = (K3 + 63) / 64;
    dim3 grid((N + 127) / 128, M / 128, 1);
    gemm_mma<<<grid, 256, GTC_SMEM>>>(abig, K3, wbig, K3, bias, C, ldc,
                                      N, K3, 0, nch, 0, flags);
}

// ---------------- launch ----------------------------------------------------
extern "C" void kernel_launch(void* const* d_in, const int* in_sizes, int n_in,
                              void* d_out, int out_size)
{
    const float* features  = (const float*)d_in[0];
    const void*  mask      = d_in[1];
    const float* inp_w     = (const float*)d_in[2];
    const float* inp_b     = (const float*)d_in[3];
    const float* norm_w    = (const float*)d_in[4];
    const float* norm_b    = (const float*)d_in[5];
    const float* in_proj_w = (const float*)d_in[6];
    const float* conv_w    = (const float*)d_in[7];
    const float* conv_b    = (const float*)d_in[8];
    const float* x_proj_w  = (const float*)d_in[9];
    const float* dt_proj_w = (const float*)d_in[10];
    const float* dt_proj_b = (const float*)d_in[11];
    const float* A_log     = (const float*)d_in[12];
    const float* Dskip     = (const float*)d_in[13];
    const float* mout_w    = (const float*)d_in[14];
    const float* out_w     = (const float*)d_in[15];
    const float* out_b     = (const float*)d_in[16];
    float* out = (float*)d_out;

    cudaFuncSetAttribute(gemm_mma, cudaFuncAttributeMaxDynamicSharedMemorySize, GTC_SMEM);

    float *px, *pxn, *pxz, *pu, *pdbc, *pdelta, *py, *pob;
    __nv_bfloat16 *pab, *pwb;
    cudaGetSymbolAddress((void**)&px,     g_x);
    cudaGetSymbolAddress((void**)&pxn,    g_xn);
    cudaGetSymbolAddress((void**)&pxz,    g_xz);
    cudaGetSymbolAddress((void**)&pu,     g_u);
    cudaGetSymbolAddress((void**)&pdbc,   g_dbc);
    cudaGetSymbolAddress((void**)&pdelta, g_delta);
    cudaGetSymbolAddress((void**)&py,     g_y);
    cudaGetSymbolAddress((void**)&pob,    g_ob);
    cudaGetSymbolAddress((void**)&pab,    g_abig);
    cudaGetSymbolAddress((void**)&pwb,    g_wbig);

    detect_mask_kernel<<<1, 256>>>((const unsigned char*)mask);

    // x = features @ inp_w^T + inp_b
    run_gemm(features, DIN_, inp_w, DIN_, inp_b, px, DM_, MROWS, DM_, DIN_, 0, pab, pwb);

    const int NPART = MROWS * DBCW;

    for (int l = 0; l < LNUM; l++) {
        layernorm_kernel<<<MROWS, 256>>>(px, norm_w + l*DM_, norm_b + l*DM_, pxn);

        // xz = xn @ in_proj_w^T
        run_gemm(pxn, DM_, in_proj_w + (size_t)l*2*DI_*DM_, DM_, nullptr,
                 pxz, 2*DI_, MROWS, 2*DI_, DM_, 0, pab, pwb);

        conv_silu_kernel<<<(unsigned)((MROWS*(size_t)(DI_/4))/256), 256>>>(
            conv_w + (size_t)l*DI_*DC_, conv_b + l*DI_);

        // dbc = u @ x_proj_w^T  — split-K x4 via gridDim.z
        {
            size_t na = (size_t)MROWS * DI_, nw = (size_t)DBCW * DI_;
            convert_split<<<(unsigned)((na + 255) / 256), 256>>>(pu, DI_, pab, MROWS, DI_, 0);
            convert_split<<<(unsigned)((nw + 255) / 256), 256>>>(
                x_proj_w + (size_t)l*DBCW*DI_, DI_, pwb, DBCW, DI_, 1);
            int K3 = 3 * DI_;
            int nchp = (K3 / 4) / 64;
            dim3 grid(1, MROWS / 128, 4);
            gemm_mma<<<grid, 256, GTC_SMEM>>>(pab, K3, pwb, K3, nullptr,
                pob, DBCW, DBCW, K3, 0, nchp, NPART, 0);
            reduce4_kernel<<<(NPART + 255) / 256, 256>>>(pdbc, pob, NPART);
        }

        // delta = softplus(dt @ dt_proj_w^T + dt_proj_b)
        run_gemm(pdbc, DBCW, dt_proj_w + (size_t)l*DI_*DTR_, DTR_,
                 dt_proj_b + l*DI_, pdelta, DI_, MROWS, DI_, DTR_, 2, pab, pwb);

        // selective scan + fused silu(z) gate
        scan_kernel<<<512, 256>>>(A_log + (size_t)l*DI_*DS_, Dskip + l*DI_);

        // x += (y*silu(z)) @ mout_w^T
        run_gemm(py, DI_, mout_w + (size_t)l*DM_*DI_, DI_, nullptr,
                 px, DM_, MROWS, DM_, DI_, 1, pab, pwb);
    }

    // ob = x @ out_w^T + out_b
    run_gemm(px, DM_, out_w, DM_, out_b, pob, DO_, MROWS, DO_, DM_, 0, pab, pwb);

    // masked mean: partials into g_xn (free), then reduce
    mean1_kernel<<<dim3(DO_/256, BSZ, MEAN_SLICES), 256>>>(pxn);
    mean2_kernel<<<dim3(DO_/256, BSZ), 256>>>(pxn, out);
}

// round 8
// speedup vs baseline: 1.8893x; 1.8893x over previous
#include <cuda_runtime.h>
#include <cuda_fp16.h>
#include <math.h>
#include <stdint.h>

#define BSZ  4
#define TLEN 2048
#define DIN_ 512
#define DM_  1024
#define DO_  1024
#define LNUM 2
#define DS_  16
#define DC_  4
#define DI_  2048
#define DTR_ 64
#define MROWS (BSZ*TLEN)
#define DBCW  (DTR_ + 2*DS_)      // 96

__device__ float g_x   [(size_t)MROWS*DM_];
__device__ float g_xn  [(size_t)MROWS*DM_];
__device__ float g_xz  [(size_t)MROWS*2*DI_];
__device__ float g_u   [(size_t)MROWS*DI_];
__device__ float g_dbc [(size_t)MROWS*DBCW];
__device__ float g_delta[(size_t)MROWS*DI_];
__device__ float g_y   [(size_t)MROWS*DI_];
__device__ float g_ob  [(size_t)MROWS*DO_];
__device__ int   g_len [BSZ];
__device__ __half g_ah[(size_t)MROWS*2048];
__device__ __half g_wh[(size_t)4096*2048];

__device__ __forceinline__ uint32_t smem_u32(const void* p) {
    uint32_t a;
    asm("{ .reg .u64 t; cvta.to.shared.u64 t, %1; cvt.u32.u64 %0, t; }" : "=r"(a) : "l"(p));
    return a;
}
__device__ __forceinline__ void cp_async16(uint32_t d, const void* g, int sz) {
    asm volatile("cp.async.cg.shared.global [%0], [%1], 16, %2;"
                 :: "r"(d), "l"(g), "r"(sz) : "memory");
}
__device__ __forceinline__ void ldm4(uint32_t* r, uint32_t addr) {
    asm volatile("ldmatrix.sync.aligned.m8n8.x4.shared.b16 {%0,%1,%2,%3}, [%4];"
        : "=r"(r[0]), "=r"(r[1]), "=r"(r[2]), "=r"(r[3]) : "r"(addr));
}
__device__ __forceinline__ void mma16816(float* d, const uint32_t* a,
                                         uint32_t b0, uint32_t b1) {
    asm volatile("mma.sync.aligned.m16n8k16.row.col.f32.f16.f16.f32 "
        "{%0,%1,%2,%3}, {%4,%5,%6,%7}, {%8,%9}, {%0,%1,%2,%3};"
        : "+f"(d[0]), "+f"(d[1]), "+f"(d[2]), "+f"(d[3])
        : "r"(a[0]), "r"(a[1]), "r"(a[2]), "r"(a[3]), "r"(b0), "r"(b1));
}

__global__ void convert_h(const float* __restrict__ src,
                          __half* __restrict__ dst, size_t n4)
{
    size_t i = (size_t)blockIdx.x * blockDim.x + threadIdx.x;
    if (i >= n4) return;
    float4 v = ((const float4*)src)[i];
    ((__half2*)dst)[i*2]   = __float22half2_rn(make_float2(v.x, v.y));
    ((__half2*)dst)[i*2+1] = __float22half2_rn(make_float2(v.z, v.w));
}

#define STAGES 3
#define STAGE_BYTES 32768u
#define GTC_SMEM (STAGES * STAGE_BYTES)

__global__ __launch_bounds__(256, 2)
void gemm_mma(const __half* __restrict__ A, int lda,
              const __half* __restrict__ W, int ldb,
              const float* __restrict__ bias,
              float* __restrict__ C, int ldc,
              int N, int K, int nch, int flags)
{
    extern __shared__ char smem[];
    const uint32_t sbase = smem_u32(smem);
    const int tid  = threadIdx.x;
    const int lane = tid & 31, wid = tid >> 5;
    const int bm = blockIdx.y << 7, bn = blockIdx.x << 7;
    const int warpM = (wid & 1) << 6;
    const int warpN = (wid >> 1) << 5;

    float acc[4][4][4];
#pragma unroll
    for (int i = 0; i < 4; i++)
#pragma unroll
        for (int j = 0; j < 4; j++)
#pragma unroll
            for (int k = 0; k < 4; k++) acc[i][j][k] = 0.f;

    const int r_a   = (lane & 7) + ((lane >> 3) & 1) * 8;
    const int cpart = lane >> 4;
    const int rx    = lane & 7;
    uint32_t a_row[4], b_row[2], csel[4];
#pragma unroll
    for (int mi = 0; mi < 4; mi++) a_row[mi] = (uint32_t)(warpM + mi*16 + r_a) * 128u;
#pragma unroll
    for (int bi = 0; bi < 2; bi++) b_row[bi] = 16384u + (uint32_t)(warpN + bi*16 + r_a) * 128u;
#pragma unroll
    for (int ks = 0; ks < 4; ks++) csel[ks] = (uint32_t)(((2*ks + cpart) ^ rx) << 4);

    const int ldch  = tid & 7;
    const int ldrow = tid >> 3;
    const uint32_t swz = (uint32_t)((ldch ^ (ldrow & 7)) << 4);

    auto load_stage = [&](int c, int stg) {
        const uint32_t sbs = sbase + (uint32_t)stg * STAGE_BYTES;
        const int kk = (c << 6) + (ldch << 3);
        const int aok = (kk < K) ? 16 : 0;
#pragma unroll
        for (int i = 0; i < 4; i++) {
            const int row = ldrow + (i << 5);
            const uint32_t off = (uint32_t)row * 128u + swz;
            cp_async16(sbs + off, A + (size_t)(bm + row) * lda + kk, aok);
            const int brow = bn + row;
            const int bok = (kk < K && brow < N) ? 16 : 0;
            cp_async16(sbs + 16384u + off, W + (size_t)(bok ? brow : 0) * ldb + kk, bok);
        }
        asm volatile("cp.async.commit_group;" ::: "memory");
    };

    for (int s = 0; s < STAGES - 1 && s < nch; s++) load_stage(s, s);

    for (int c = 0; c < nch; c++) {
        asm volatile("cp.async.wait_group %0;" :: "n"(STAGES - 2) : "memory");
        __syncthreads();
        const uint32_t sA = sbase + (uint32_t)(c % STAGES) * STAGE_BYTES;
#pragma unroll
        for (int ks = 0; ks < 4; ks++) {
            uint32_t af[4][4], bf[2][4];
#pragma unroll
            for (int mi = 0; mi < 4; mi++) ldm4(af[mi], sA + a_row[mi] + csel[ks]);
#pragma unroll
            for (int bi = 0; bi < 2; bi++) ldm4(bf[bi], sA + b_row[bi] + csel[ks]);
#pragma unroll
            for (int mi = 0; mi < 4; mi++) {
#pragma unroll
                for (int ni = 0; ni < 4; ni++) {
                    const int bi = ni >> 1, sel = ni & 1;
                    mma16816(acc[mi][ni], af[mi], bf[bi][sel], bf[bi][sel + 2]);
                }
            }
        }
        if (c + STAGES - 1 < nch) load_stage(c + STAGES - 1, (c + STAGES - 1) % STAGES);
    }

    const int g = lane >> 2;
    const int ncol = (lane & 3) * 2;
#pragma unroll
    for (int mi = 0; mi < 4; mi++) {
        const int m0 = bm + warpM + mi*16 + g;
#pragma unroll
        for (int ni = 0; ni < 4; ni++) {
            const int n = bn + warpN + ni*8 + ncol;
            if (n >= N) continue;
            float v[4] = {acc[mi][ni][0], acc[mi][ni][1], acc[mi][ni][2], acc[mi][ni][3]};
            if (bias) {
                float b0 = bias[n], b1 = bias[n+1];
                v[0] += b0; v[1] += b1; v[2] += b0; v[3] += b1;
            }
            if (flags & 2) {
#pragma unroll
                for (int k = 0; k < 4; k++)
                    v[k] = (v[k] > 20.f) ? v[k] : log1pf(expf(v[k]));
            }
            float* p0 = C + (size_t)m0 * ldc + n;
            float* p1 = C + (size_t)(m0 + 8) * ldc + n;
            if (flags & 1) {
                float2 o0 = *(const float2*)p0, o1 = *(const float2*)p1;
                v[0] += o0.x; v[1] += o0.y; v[2] += o1.x; v[3] += o1.y;
            }
            *(float2*)p0 = make_float2(v[0], v[1]);
            *(float2*)p1 = make_float2(v[2], v[3]);
        }
    }
}

__global__ void detect_mask_kernel(const unsigned char* __restrict__ mb) {
    __shared__ int s_weird, s_off, s_cnt[BSZ];
    int tid = threadIdx.x;
    if (tid == 0) { s_weird = 0; s_off = 0; }
    if (tid < BSZ) s_cnt[tid] = 0;
    __syncthreads();
    for (int i = tid; i < BSZ*TLEN; i += blockDim.x) {
        unsigned char c = mb[i];
        if (c > 1) s_weird = 1;
        else if (c && (i & 3)) s_off = 1;
    }
    __syncthreads();
    int mode = s_weird ? 2 : (s_off ? 0 : 1);
    for (int i = tid; i < BSZ*TLEN; i += blockDim.x) {
        int b = i / TLEN;
        int v;
        if (mode == 0)      v = mb[i];
        else if (mode == 1) v = ((const int*)mb)[i];
        else                v = (((const float*)mb)[i] != 0.0f);
        if (!v) atomicAdd(&s_cnt[b], 1);
    }
    __syncthreads();
    if (tid < BSZ) g_len[tid] = s_cnt[tid];
}

__global__ void layernorm_kernel(const float* __restrict__ x,
                                 const float* __restrict__ w,
                                 const float* __restrict__ bb,
                                 float* __restrict__ y)
{
    int row = blockIdx.x, tid = threadIdx.x;
    const float* xr = x + (size_t)row * DM_;
    float4 v = *(const float4*)(xr + tid * 4);
    float s  = v.x + v.y + v.z + v.w;
    float ss = v.x*v.x + v.y*v.y + v.z*v.z + v.w*v.w;
#pragma unroll
    for (int o = 16; o > 0; o >>= 1) {
        s  += __shfl_xor_sync(0xffffffffu, s, o);
        ss += __shfl_xor_sync(0xffffffffu, ss, o);
    }
    __shared__ float rs_[8], rss[8];
    int wid = tid >> 5, lane = tid & 31;
    if (lane == 0) { rs_[wid] = s; rss[wid] = ss; }
    __syncthreads();
    if (tid == 0) {
        float ts = 0.f, tss = 0.f;
        for (int i = 0; i < 8; i++) { ts += rs_[i]; tss += rss[i]; }
        rs_[0] = ts; rss[0] = tss;
    }
    __syncthreads();
    float mu  = rs_[0] * (1.f / DM_);
    float var = rss[0] * (1.f / DM_) - mu * mu;
    float inv = rsqrtf(var + 1e-5f);
    float4 wv = *(const float4*)(w + tid * 4);
    float4 bv = *(const float4*)(bb + tid * 4);
    float4 o;
    o.x = (v.x - mu) * inv * wv.x + bv.x;
    o.y = (v.y - mu) * inv * wv.y + bv.y;
    o.z = (v.z - mu) * inv * wv.z + bv.z;
    o.w = (v.w - mu) * inv * wv.w + bv.w;
    *(float4*)(y + (size_t)row * DM_ + tid * 4) = o;
}

__global__ void conv_silu_kernel(const float* __restrict__ cw,
                                 const float* __restrict__ cb)
{
    size_t idx = (size_t)blockIdx.x * blockDim.x + threadIdx.x;
    int d = (int)(idx % DI_);
    size_t r = idx / DI_;
    int t = (int)(r % TLEN);
    const size_t base = r * (size_t)(2 * DI_) + d;
    float acc = cb[d];
#pragma unroll
    for (int j = 0; j < DC_; j++) {
        int tt = t - (DC_ - 1) + j;
        if (tt >= 0)
            acc += g_xz[base + (size_t)(j - (DC_ - 1)) * (2 * DI_)] * cw[d * DC_ + j];
    }
    float sg = 1.f / (1.f + __expf(-acc));
    g_u[r * DI_ + d] = acc * sg;
}

__global__ void scan_kernel(const float* __restrict__ Alog,
                            const float* __restrict__ Dp)
{
    int gw   = (int)((blockIdx.x * blockDim.x + threadIdx.x) >> 5);
    int lane = threadIdx.x & 31;
    int b  = gw >> 10;
    int dp = gw & 1023;
    int s  = lane & 15;
    int half = lane >> 4;
    int d = dp * 2 + half;

    float Av = -expf(Alog[d * DS_ + s]);
    float Dv = Dp[d];
    float h = 0.f;

    for (int t = 0; t < TLEN; t++) {
        size_t row = (size_t)b * TLEN + t;
        float delta = g_delta[row * DI_ + d];
        float u     = g_u    [row * DI_ + d];
        float Bv = g_dbc[row * DBCW + DTR_ + s];
        float Cv = g_dbc[row * DBCW + DTR_ + DS_ + s];
        float e = __expf(delta * Av);
        h = h * e + (delta * u) * Bv;
        float p = h * Cv;
        p += __shfl_xor_sync(0xffffffffu, p, 1);
        p += __shfl_xor_sync(0xffffffffu, p, 2);
        p += __shfl_xor_sync(0xffffffffu, p, 4);
        p += __shfl_xor_sync(0xffffffffu, p, 8);
        if (s == 0) g_y[row * DI_ + d] = p + u * Dv;
    }
}

__global__ void gate_kernel()
{
    size_t idx = (size_t)blockIdx.x * blockDim.x + threadIdx.x;
    int d = (int)(idx % DI_);
    size_t r = idx / DI_;
    float z = g_xz[r * (size_t)(2 * DI_) + DI_ + d];
    float sg = z / (1.f + __expf(-z));
    g_y[idx] *= sg;
}

__global__ void mean_kernel(float* __restrict__ out)
{
    int b = blockIdx.y;
    int o = blockIdx.x * blockDim.x + threadIdx.x;
    int len = g_len[b];
    if (len < 1) len = 1;
    const float* p = g_ob + ((size_t)b * TLEN) * DO_ + o;
    float sum = 0.f;
    for (int t = 0; t < len; t++) sum += p[(size_t)t * DO_];
    out[b * DO_ + o] = sum / (float)len;
}

// Convert (rows*width) contiguous fp32 -> fp16, then GEMM over K<=width cols
// with lda=ldb=width. For all call sites width==K except dt (width=96, K=64).
static void run_gemm_w(const float* A, int awidth, const float* W, int wwidth,
                       const float* bias, float* C, int ldc,
                       int M, int N, int K, int flags,
                       __half* ah, __half* wh)
{
    size_t na4 = ((size_t)M * awidth) / 4, nw4 = ((size_t)N * wwidth) / 4;
    convert_h<<<(unsigned)((na4 + 255) / 256), 256>>>(A, ah, na4);
    convert_h<<<(unsigned)((nw4 + 255) / 256), 256>>>(W, wh, nw4);
    int nch = (K + 63) / 64;
    if (nch < 2) nch = 2;
    dim3 grid((N + 127) / 128, M / 128);
    gemm_mma<<<grid, 256, GTC_SMEM>>>(ah, awidth, wh, wwidth, bias, C, ldc,
                                      N, K, nch, flags);
}

extern "C" void kernel_launch(void* const* d_in, const int* in_sizes, int n_in,
                              void* d_out, int out_size)
{
    const float* features  = (const float*)d_in[0];
    const void*  mask      = d_in[1];
    const float* inp_w     = (const float*)d_in[2];
    const float* inp_b     = (const float*)d_in[3];
    const float* norm_w    = (const float*)d_in[4];
    const float* norm_b    = (const float*)d_in[5];
    const float* in_proj_w = (const float*)d_in[6];
    const float* conv_w    = (const float*)d_in[7];
    const float* conv_b    = (const float*)d_in[8];
    const float* x_proj_w  = (const float*)d_in[9];
    const float* dt_proj_w = (const float*)d_in[10];
    const float* dt_proj_b = (const float*)d_in[11];
    const float* A_log     = (const float*)d_in[12];
    const float* Dskip     = (const float*)d_in[13];
    const float* mout_w    = (const float*)d_in[14];
    const float* out_w     = (const float*)d_in[15];
    const float* out_b     = (const float*)d_in[16];
    float* out = (float*)d_out;

    cudaFuncSetAttribute(gemm_mma, cudaFuncAttributeMaxDynamicSharedMemorySize, GTC_SMEM);

    float *px, *pxn, *pxz, *pu, *pdbc, *pdelta, *py, *pob;
    __half *pah, *pwh;
    cudaGetSymbolAddress((void**)&px,     g_x);
    cudaGetSymbolAddress((void**)&pxn,    g_xn);
    cudaGetSymbolAddress((void**)&pxz,    g_xz);
    cudaGetSymbolAddress((void**)&pu,     g_u);
    cudaGetSymbolAddress((void**)&pdbc,   g_dbc);
    cudaGetSymbolAddress((void**)&pdelta, g_delta);
    cudaGetSymbolAddress((void**)&py,     g_y);
    cudaGetSymbolAddress((void**)&pob,    g_ob);
    cudaGetSymbolAddress((void**)&pah,    g_ah);
    cudaGetSymbolAddress((void**)&pwh,    g_wh);

    detect_mask_kernel<<<1, 256>>>((const unsigned char*)mask);

    run_gemm_w(features, DIN_, inp_w, DIN_, inp_b, px, DM_,
               MROWS, DM_, DIN_, 0, pah, pwh);

    for (int l = 0; l < LNUM; l++) {
        layernorm_kernel<<<MROWS, 256>>>(px, norm_w + l*DM_, norm_b + l*DM_, pxn);

        run_gemm_w(pxn, DM_, in_proj_w + (size_t)l*2*DI_*DM_, DM_, nullptr,
                   pxz, 2*DI_, MROWS, 2*DI_, DM_, 0, pah, pwh);

        conv_silu_kernel<<<(unsigned)((MROWS*(size_t)DI_)/256), 256>>>(
            conv_w + (size_t)l*DI_*DC_, conv_b + l*DI_);

        run_gemm_w(pu, DI_, x_proj_w + (size_t)l*DBCW*DI_, DI_, nullptr,
                   pdbc, DBCW, MROWS, DBCW, DI_, 0, pah, pwh);

        // dt: A = dbc rows (width 96, use first K=64 cols), W width 64
        run_gemm_w(pdbc, DBCW, dt_proj_w + (size_t)l*DI_*DTR_, DTR_,
                   dt_proj_b + l*DI_, pdelta, DI_, MROWS, DI_, DTR_, 2, pah, pwh);

        scan_kernel<<<512, 256>>>(A_log + (size_t)l*DI_*DS_, Dskip + l*DI_);

        gate_kernel<<<(unsigned)((MROWS*(size_t)DI_)/256), 256>>>();

        run_gemm_w(py, DI_, mout_w + (size_t)l*DM_*DI_, DI_, nullptr,
                   px, DM_, MROWS, DM_, DI_, 1, pah, pwh);
    }

    run_gemm_w(px, DM_, out_w, DM_, out_b, pob, DO_,
               MROWS, DO_, DM_, 0, pah, pwh);

    mean_kernel<<<dim3(DO_/256, BSZ), 256>>>(out);
}

// round 9
// speedup vs baseline: 1.9522x; 1.0333x over previous
#include <cuda_runtime.h>
#include <cuda_fp16.h>
#include <math.h>
#include <stdint.h>

#define BSZ  4
#define TLEN 2048
#define DIN_ 512
#define DM_  1024
#define DO_  1024
#define LNUM 2
#define DS_  16
#define DC_  4
#define DI_  2048
#define DTR_ 64
#define MROWS (BSZ*TLEN)
#define DBCW  (DTR_ + 2*DS_)      // 96

__device__ float g_x   [(size_t)MROWS*DM_];
__device__ float g_xz  [(size_t)MROWS*2*DI_];
__device__ float g_u   [(size_t)MROWS*DI_];
__device__ float g_dbc [(size_t)MROWS*DBCW];
__device__ float g_delta[(size_t)MROWS*DI_];
__device__ float g_y   [(size_t)MROWS*DI_];
__device__ float g_ob  [(size_t)MROWS*DO_];
__device__ int   g_len [BSZ];
__device__ __half g_ah[(size_t)MROWS*2048];    // activation fp16 staging
__device__ __half g_wh[(size_t)4096*2048];     // weight fp16 staging
__device__ __half g_dh[(size_t)MROWS*DBCW];    // dbc fp16 (dt GEMM A)

__device__ __forceinline__ uint32_t smem_u32(const void* p) {
    uint32_t a;
    asm("{ .reg .u64 t; cvta.to.shared.u64 t, %1; cvt.u32.u64 %0, t; }" : "=r"(a) : "l"(p));
    return a;
}
__device__ __forceinline__ void cp_async16(uint32_t d, const void* g, int sz) {
    asm volatile("cp.async.cg.shared.global [%0], [%1], 16, %2;"
                 :: "r"(d), "l"(g), "r"(sz) : "memory");
}
__device__ __forceinline__ void ldm4(uint32_t* r, uint32_t addr) {
    asm volatile("ldmatrix.sync.aligned.m8n8.x4.shared.b16 {%0,%1,%2,%3}, [%4];"
        : "=r"(r[0]), "=r"(r[1]), "=r"(r[2]), "=r"(r[3]) : "r"(addr));
}
__device__ __forceinline__ void mma16816(float* d, const uint32_t* a,
                                         uint32_t b0, uint32_t b1) {
    asm volatile("mma.sync.aligned.m16n8k16.row.col.f32.f16.f16.f32 "
        "{%0,%1,%2,%3}, {%4,%5,%6,%7}, {%8,%9}, {%0,%1,%2,%3};"
        : "+f"(d[0]), "+f"(d[1]), "+f"(d[2]), "+f"(d[3])
        : "r"(a[0]), "r"(a[1]), "r"(a[2]), "r"(a[3]), "r"(b0), "r"(b1));
}

__global__ void convert_h(const float* __restrict__ src,
                          __half* __restrict__ dst, size_t n4)
{
    size_t i = (size_t)blockIdx.x * blockDim.x + threadIdx.x;
    if (i >= n4) return;
    float4 v = ((const float4*)src)[i];
    ((__half2*)dst)[i*2]   = __float22half2_rn(make_float2(v.x, v.y));
    ((__half2*)dst)[i*2+1] = __float22half2_rn(make_float2(v.z, v.w));
}

#define STAGES 3
#define STAGE_BYTES 32768u
#define GTC_SMEM (STAGES * STAGE_BYTES)

// C = A(MxK, lda) * W(NxK, ldb)^T
// flags: bit0 accumulate, bit1 softplus. hout!=null -> also write fp16 C copy.
__global__ __launch_bounds__(256, 2)
void gemm_mma(const __half* __restrict__ A, int lda,
              const __half* __restrict__ W, int ldb,
              const float* __restrict__ bias,
              float* __restrict__ C, int ldc,
              __half* __restrict__ hout, int hld,
              int N, int K, int nch, int flags)
{
    extern __shared__ char smem[];
    const uint32_t sbase = smem_u32(smem);
    const int tid  = threadIdx.x;
    const int lane = tid & 31, wid = tid >> 5;
    const int bm = blockIdx.y << 7, bn = blockIdx.x << 7;
    const int warpM = (wid & 1) << 6;
    const int warpN = (wid >> 1) << 5;

    float acc[4][4][4];
#pragma unroll
    for (int i = 0; i < 4; i++)
#pragma unroll
        for (int j = 0; j < 4; j++)
#pragma unroll
            for (int k = 0; k < 4; k++) acc[i][j][k] = 0.f;

    const int r_a   = (lane & 7) + ((lane >> 3) & 1) * 8;
    const int cpart = lane >> 4;
    const int rx    = lane & 7;
    uint32_t a_row[4], b_row[2], csel[4];
#pragma unroll
    for (int mi = 0; mi < 4; mi++) a_row[mi] = (uint32_t)(warpM + mi*16 + r_a) * 128u;
#pragma unroll
    for (int bi = 0; bi < 2; bi++) b_row[bi] = 16384u + (uint32_t)(warpN + bi*16 + r_a) * 128u;
#pragma unroll
    for (int ks = 0; ks < 4; ks++) csel[ks] = (uint32_t)(((2*ks + cpart) ^ rx) << 4);

    const int ldch  = tid & 7;
    const int ldrow = tid >> 3;
    const uint32_t swz = (uint32_t)((ldch ^ (ldrow & 7)) << 4);

    auto load_stage = [&](int c, int stg) {
        const uint32_t sbs = sbase + (uint32_t)stg * STAGE_BYTES;
        const int kk = (c << 6) + (ldch << 3);
        const int aok = (kk < K) ? 16 : 0;
#pragma unroll
        for (int i = 0; i < 4; i++) {
            const int row = ldrow + (i << 5);
            const uint32_t off = (uint32_t)row * 128u + swz;
            cp_async16(sbs + off, A + (size_t)(bm + row) * lda + kk, aok);
            const int brow = bn + row;
            const int bok = (kk < K && brow < N) ? 16 : 0;
            cp_async16(sbs + 16384u + off, W + (size_t)(bok ? brow : 0) * ldb + kk, bok);
        }
        asm volatile("cp.async.commit_group;" ::: "memory");
    };

    for (int s = 0; s < STAGES - 1 && s < nch; s++) load_stage(s, s);

    for (int c = 0; c < nch; c++) {
        asm volatile("cp.async.wait_group %0;" :: "n"(STAGES - 2) : "memory");
        __syncthreads();
        const uint32_t sA = sbase + (uint32_t)(c % STAGES) * STAGE_BYTES;
#pragma unroll
        for (int ks = 0; ks < 4; ks++) {
            uint32_t af[4][4], bf[2][4];
#pragma unroll
            for (int mi = 0; mi < 4; mi++) ldm4(af[mi], sA + a_row[mi] + csel[ks]);
#pragma unroll
            for (int bi = 0; bi < 2; bi++) ldm4(bf[bi], sA + b_row[bi] + csel[ks]);
#pragma unroll
            for (int mi = 0; mi < 4; mi++) {
#pragma unroll
                for (int ni = 0; ni < 4; ni++) {
                    const int bi = ni >> 1, sel = ni & 1;
                    mma16816(acc[mi][ni], af[mi], bf[bi][sel], bf[bi][sel + 2]);
                }
            }
        }
        if (c + STAGES - 1 < nch) load_stage(c + STAGES - 1, (c + STAGES - 1) % STAGES);
    }

    const int g = lane >> 2;
    const int ncol = (lane & 3) * 2;
#pragma unroll
    for (int mi = 0; mi < 4; mi++) {
        const int m0 = bm + warpM + mi*16 + g;
#pragma unroll
        for (int ni = 0; ni < 4; ni++) {
            const int n = bn + warpN + ni*8 + ncol;
            if (n >= N) continue;
            float v[4] = {acc[mi][ni][0], acc[mi][ni][1], acc[mi][ni][2], acc[mi][ni][3]};
            if (bias) {
                float b0 = bias[n], b1 = bias[n+1];
                v[0] += b0; v[1] += b1; v[2] += b0; v[3] += b1;
            }
            if (flags & 2) {
#pragma unroll
                for (int k = 0; k < 4; k++)
                    v[k] = (v[k] > 20.f) ? v[k] : log1pf(expf(v[k]));
            }
            float* p0 = C + (size_t)m0 * ldc + n;
            float* p1 = C + (size_t)(m0 + 8) * ldc + n;
            if (flags & 1) {
                float2 o0 = *(const float2*)p0, o1 = *(const float2*)p1;
                v[0] += o0.x; v[1] += o0.y; v[2] += o1.x; v[3] += o1.y;
            }
            *(float2*)p0 = make_float2(v[0], v[1]);
            *(float2*)p1 = make_float2(v[2], v[3]);
            if (hout) {
                *(__half2*)(hout + (size_t)m0 * hld + n) =
                    __float22half2_rn(make_float2(v[0], v[1]));
                *(__half2*)(hout + (size_t)(m0 + 8) * hld + n) =
                    __float22half2_rn(make_float2(v[2], v[3]));
            }
        }
    }
}

__global__ void detect_mask_kernel(const unsigned char* __restrict__ mb) {
    __shared__ int s_weird, s_off, s_cnt[BSZ];
    int tid = threadIdx.x;
    if (tid == 0) { s_weird = 0; s_off = 0; }
    if (tid < BSZ) s_cnt[tid] = 0;
    __syncthreads();
    for (int i = tid; i < BSZ*TLEN; i += blockDim.x) {
        unsigned char c = mb[i];
        if (c > 1) s_weird = 1;
        else if (c && (i & 3)) s_off = 1;
    }
    __syncthreads();
    int mode = s_weird ? 2 : (s_off ? 0 : 1);
    for (int i = tid; i < BSZ*TLEN; i += blockDim.x) {
        int b = i / TLEN;
        int v;
        if (mode == 0)      v = mb[i];
        else if (mode == 1) v = ((const int*)mb)[i];
        else                v = (((const float*)mb)[i] != 0.0f);
        if (!v) atomicAdd(&s_cnt[b], 1);
    }
    __syncthreads();
    if (tid < BSZ) g_len[tid] = s_cnt[tid];
}

// layernorm, writing fp16 directly into the GEMM A buffer
__global__ void layernorm_h_kernel(const float* __restrict__ x,
                                   const float* __restrict__ w,
                                   const float* __restrict__ bb,
                                   __half* __restrict__ y)
{
    int row = blockIdx.x, tid = threadIdx.x;
    const float* xr = x + (size_t)row * DM_;
    float4 v = *(const float4*)(xr + tid * 4);
    float s  = v.x + v.y + v.z + v.w;
    float ss = v.x*v.x + v.y*v.y + v.z*v.z + v.w*v.w;
#pragma unroll
    for (int o = 16; o > 0; o >>= 1) {
        s  += __shfl_xor_sync(0xffffffffu, s, o);
        ss += __shfl_xor_sync(0xffffffffu, ss, o);
    }
    __shared__ float rs_[8], rss[8];
    int wid = tid >> 5, lane = tid & 31;
    if (lane == 0) { rs_[wid] = s; rss[wid] = ss; }
    __syncthreads();
    if (tid == 0) {
        float ts = 0.f, tss = 0.f;
        for (int i = 0; i < 8; i++) { ts += rs_[i]; tss += rss[i]; }
        rs_[0] = ts; rss[0] = tss;
    }
    __syncthreads();
    float mu  = rs_[0] * (1.f / DM_);
    float var = rss[0] * (1.f / DM_) - mu * mu;
    float inv = rsqrtf(var + 1e-5f);
    float4 wv = *(const float4*)(w + tid * 4);
    float4 bv = *(const float4*)(bb + tid * 4);
    float o0 = (v.x - mu) * inv * wv.x + bv.x;
    float o1 = (v.y - mu) * inv * wv.y + bv.y;
    float o2 = (v.z - mu) * inv * wv.z + bv.z;
    float o3 = (v.w - mu) * inv * wv.w + bv.w;
    __half* yr = y + (size_t)row * DM_ + tid * 4;
    *(__half2*)(yr)     = __float22half2_rn(make_float2(o0, o1));
    *(__half2*)(yr + 2) = __float22half2_rn(make_float2(o2, o3));
}

// causal depthwise conv + bias + silu; dual write fp32 (scan) + fp16 (GEMM A)
__global__ void conv_silu_kernel(const float* __restrict__ cw,
                                 const float* __restrict__ cb)
{
    size_t idx = (size_t)blockIdx.x * blockDim.x + threadIdx.x;
    int d = (int)(idx % DI_);
    size_t r = idx / DI_;
    int t = (int)(r % TLEN);
    const size_t base = r * (size_t)(2 * DI_) + d;
    float acc = cb[d];
#pragma unroll
    for (int j = 0; j < DC_; j++) {
        int tt = t - (DC_ - 1) + j;
        if (tt >= 0)
            acc += g_xz[base + (size_t)(j - (DC_ - 1)) * (2 * DI_)] * cw[d * DC_ + j];
    }
    float sg = 1.f / (1.f + __expf(-acc));
    float u = acc * sg;
    g_u[r * DI_ + d] = u;
    g_ah[r * DI_ + d] = __float2half(u);
}

__global__ void scan_kernel(const float* __restrict__ Alog,
                            const float* __restrict__ Dp)
{
    int gw   = (int)((blockIdx.x * blockDim.x + threadIdx.x) >> 5);
    int lane = threadIdx.x & 31;
    int b  = gw >> 10;
    int dp = gw & 1023;
    int s  = lane & 15;
    int half = lane >> 4;
    int d = dp * 2 + half;

    float Av = -expf(Alog[d * DS_ + s]);
    float Dv = Dp[d];
    float h = 0.f;

    for (int t = 0; t < TLEN; t++) {
        size_t row = (size_t)b * TLEN + t;
        float delta = g_delta[row * DI_ + d];
        float u     = g_u    [row * DI_ + d];
        float Bv = g_dbc[row * DBCW + DTR_ + s];
        float Cv = g_dbc[row * DBCW + DTR_ + DS_ + s];
        float e = __expf(delta * Av);
        h = h * e + (delta * u) * Bv;
        float p = h * Cv;
        p += __shfl_xor_sync(0xffffffffu, p, 1);
        p += __shfl_xor_sync(0xffffffffu, p, 2);
        p += __shfl_xor_sync(0xffffffffu, p, 4);
        p += __shfl_xor_sync(0xffffffffu, p, 8);
        if (s == 0) g_y[row * DI_ + d] = p + u * Dv;
    }
}

// gate: ah = fp16( y * silu(z) )  — fp16 feeds the mout GEMM directly
__global__ void gate_h_kernel()
{
    size_t idx = (size_t)blockIdx.x * blockDim.x + threadIdx.x;
    int d = (int)(idx % DI_);
    size_t r = idx / DI_;
    float z = g_xz[r * (size_t)(2 * DI_) + DI_ + d];
    float sg = z / (1.f + __expf(-z));
    g_ah[idx] = __float2half(g_y[idx] * sg);
}

__global__ void mean_kernel(float* __restrict__ out)
{
    int b = blockIdx.y;
    int o = blockIdx.x * blockDim.x + threadIdx.x;
    int len = g_len[b];
    if (len < 1) len = 1;
    const float* p = g_ob + ((size_t)b * TLEN) * DO_ + o;
    float sum = 0.f;
    for (int t = 0; t < len; t++) sum += p[(size_t)t * DO_];
    out[b * DO_ + o] = sum / (float)len;
}

static void launch_gemm(const __half* A, int lda, const __half* W, int ldb,
                        const float* bias, float* C, int ldc,
                        __half* hout, int hld,
                        int M, int N, int K, int flags)
{
    int nch = (K + 63) / 64;
    if (nch < 2) nch = 2;
    dim3 grid((N + 127) / 128, M / 128);
    gemm_mma<<<grid, 256, GTC_SMEM>>>(A, lda, W, ldb, bias, C, ldc,
                                      hout, hld, N, K, nch, flags);
}
static void conv_w(const float* W, __half* wh, size_t n) {
    convert_h<<<(unsigned)((n/4 + 255) / 256), 256>>>(W, wh, n/4);
}

extern "C" void kernel_launch(void* const* d_in, const int* in_sizes, int n_in,
                              void* d_out, int out_size)
{
    const float* features  = (const float*)d_in[0];
    const void*  mask      = d_in[1];
    const float* inp_w     = (const float*)d_in[2];
    const float* inp_b     = (const float*)d_in[3];
    const float* norm_w    = (const float*)d_in[4];
    const float* norm_b    = (const float*)d_in[5];
    const float* in_proj_w = (const float*)d_in[6];
    const float* conv_w_   = (const float*)d_in[7];
    const float* conv_b    = (const float*)d_in[8];
    const float* x_proj_w  = (const float*)d_in[9];
    const float* dt_proj_w = (const float*)d_in[10];
    const float* dt_proj_b = (const float*)d_in[11];
    const float* A_log     = (const float*)d_in[12];
    const float* Dskip     = (const float*)d_in[13];
    const float* mout_w    = (const float*)d_in[14];
    const float* out_w     = (const float*)d_in[15];
    const float* out_b     = (const float*)d_in[16];
    float* out = (float*)d_out;

    cudaFuncSetAttribute(gemm_mma, cudaFuncAttributeMaxDynamicSharedMemorySize, GTC_SMEM);

    float *px, *pxz, *pu, *pdbc, *pdelta, *py, *pob;
    __half *pah, *pwh, *pdh;
    cudaGetSymbolAddress((void**)&px,     g_x);
    cudaGetSymbolAddress((void**)&pxz,    g_xz);
    cudaGetSymbolAddress((void**)&pu,     g_u);
    cudaGetSymbolAddress((void**)&pdbc,   g_dbc);
    cudaGetSymbolAddress((void**)&pdelta, g_delta);
    cudaGetSymbolAddress((void**)&py,     g_y);
    cudaGetSymbolAddress((void**)&pob,    g_ob);
    cudaGetSymbolAddress((void**)&pah,    g_ah);
    cudaGetSymbolAddress((void**)&pwh,    g_wh);
    cudaGetSymbolAddress((void**)&pdh,    g_dh);

    detect_mask_kernel<<<1, 256>>>((const unsigned char*)mask);

    // x = features @ inp_w^T + inp_b
    convert_h<<<(unsigned)(((size_t)MROWS*DIN_/4 + 255)/256), 256>>>(
        features, pah, (size_t)MROWS*DIN_/4);
    conv_w(inp_w, pwh, (size_t)DM_*DIN_);
    launch_gemm(pah, DIN_, pwh, DIN_, inp_b, px, DM_, nullptr, 0,
                MROWS, DM_, DIN_, 0);

    for (int l = 0; l < LNUM; l++) {
        // xn (fp16 direct)
        layernorm_h_kernel<<<MROWS, 256>>>(px, norm_w + l*DM_, norm_b + l*DM_, pah);

        // xz = xn @ in_proj_w^T
        conv_w(in_proj_w + (size_t)l*2*DI_*DM_, pwh, (size_t)2*DI_*DM_);
        launch_gemm(pah, DM_, pwh, DM_, nullptr, pxz, 2*DI_, nullptr, 0,
                    MROWS, 2*DI_, DM_, 0);

        // u = silu(conv(xi)+b): fp32 for scan + fp16 into ah for x_proj GEMM
        conv_silu_kernel<<<(unsigned)((MROWS*(size_t)DI_)/256), 256>>>(
            conv_w_ + (size_t)l*DI_*DC_, conv_b + l*DI_);

        // dbc = u @ x_proj_w^T  (fp32 + fp16 dual write)
        conv_w(x_proj_w + (size_t)l*DBCW*DI_, pwh, (size_t)DBCW*DI_);
        launch_gemm(pah, DI_, pwh, DI_, nullptr, pdbc, DBCW, pdh, DBCW,
                    MROWS, DBCW, DI_, 0);

        // delta = softplus(dt @ dt_proj_w^T + dt_proj_b)  (A = dh, lda=96, K=64)
        conv_w(dt_proj_w + (size_t)l*DI_*DTR_, pwh, (size_t)DI_*DTR_);
        launch_gemm(pdh, DBCW, pwh, DTR_, dt_proj_b + l*DI_, pdelta, DI_,
                    nullptr, 0, MROWS, DI_, DTR_, 2);

        // selective scan
        scan_kernel<<<512, 256>>>(A_log + (size_t)l*DI_*DS_, Dskip + l*DI_);

        // gated y (fp16 direct into ah)
        gate_h_kernel<<<(unsigned)((MROWS*(size_t)DI_)/256), 256>>>();

        // x += y_gated @ mout_w^T
        conv_w(mout_w + (size_t)l*DM_*DI_, pwh, (size_t)DM_*DI_);
        launch_gemm(pah, DI_, pwh, DI_, nullptr, px, DM_, nullptr, 0,
                    MROWS, DM_, DI_, 1);
    }

    // ob = x @ out_w^T + out_b
    convert_h<<<(unsigned)(((size_t)MROWS*DM_/4 + 255)/256), 256>>>(
        px, pah, (size_t)MROWS*DM_/4);
    conv_w(out_w, pwh, (size_t)DO_*DM_);
    launch_gemm(pah, DM_, pwh, DM_, out_b, pob, DO_, nullptr, 0,
                MROWS, DO_, DM_, 0);

    mean_kernel<<<dim3(DO_/256, BSZ), 256>>>(out);
}